// round 15
// baseline (speedup 1.0000x reference)
#include <cuda_runtime.h>
#include <cuda_bf16.h>
#include <cstdint>

#define BATCH   2048
#define FLAT_IN 512
#define PROJ    256
#define HEADS   16384
#define ACT     64
#define NBLK    (HEADS / 32)          // 512 32-head blocks per row

// ---------------- scratch (__device__ globals; allocs are forbidden) -------
__device__ float          g_s[BATCH * PROJ];          // projected state fp32
__device__ __nv_bfloat16  g_s_bf[BATCH * PROJ];       // projected state bf16
__device__ __nv_bfloat16  g_mem_bf[HEADS * PROJ];     // memories bf16
__device__ float          g_blockmax[BATCH * NBLK];   // per-row per-32-head max
__device__ unsigned       g_rowmax[BATCH];            // per-row okey(max sim)

// ---------------- helpers ---------------------------------------------------
__device__ __forceinline__ uint32_t smem_u32(const void* p) {
    uint32_t a;
    asm("{ .reg .u64 t; cvta.to.shared.u64 t, %1; cvt.u32.u64 %0, t; }"
        : "=r"(a) : "l"(p));
    return a;
}
__device__ __forceinline__ unsigned okey(float f) {
    unsigned u = __float_as_uint(f);
    return (u & 0x80000000u) ? ~u : (u | 0x80000000u);
}
__device__ __forceinline__ float unkey(unsigned k) {
    unsigned u = (k & 0x80000000u) ? (k & 0x7FFFFFFFu) : ~k;
    return __uint_as_float(u);
}
__device__ __forceinline__ void ffma2(unsigned long long& d,
                                      unsigned long long a,
                                      unsigned long long b) {
    asm("fma.rn.f32x2 %0, %1, %2, %0;" : "+l"(d) : "l"(a), "l"(b));
}
__device__ __forceinline__ unsigned long long pack2(float x) {
    unsigned long long r;
    asm("mov.b64 %0, {%1, %1};" : "=l"(r) : "f"(x));
    return r;
}

#define LDSM4(d, addr)                                                         \
    asm volatile("ldmatrix.sync.aligned.m8n8.x4.shared.b16 {%0,%1,%2,%3}, [%4];" \
        : "=r"((d)[0]), "=r"((d)[1]), "=r"((d)[2]), "=r"((d)[3]) : "r"(addr))

#define MMA_BF16(c, a, br0, br1)                                               \
    asm volatile("mma.sync.aligned.m16n8k16.row.col.f32.bf16.bf16.f32 "        \
        "{%0,%1,%2,%3}, {%4,%5,%6,%7}, {%8,%9}, {%0,%1,%2,%3};"                \
        : "+f"((c)[0]), "+f"((c)[1]), "+f"((c)[2]), "+f"((c)[3])               \
        : "r"((a)[0]), "r"((a)[1]), "r"((a)[2]), "r"((a)[3]),                  \
          "r"(br0), "r"(br1))

#define CVT_BF16X2(dst, hi, lo)                                                \
    asm("cvt.rn.satfinite.bf16x2.f32 %0, %1, %2;" : "=r"(dst) : "f"(hi), "f"(lo))

// ---------------------------------------------------------------------------
// K1 (fused): blocks [0,2048): mems fp32->bf16 (+ zero g_rowmax);
//             blocks [2048, 2176): proj s = state @ rp (R4-certified body).
// ---------------------------------------------------------------------------
__global__ __launch_bounds__(256) void prep_kernel(const float* __restrict__ state,
                                                   const float* __restrict__ rp,
                                                   const float* __restrict__ mem) {
    __shared__ __align__(16) float As[64 * 36];
    __shared__ __align__(16) float Bs[32 * 68];

    const int bid = blockIdx.x;
    const int tid = threadIdx.x;

    if (bid < 2048) {
        // ---- conv part: 8 elems/thread over mems ---------------------------
        size_t i = ((size_t)bid * 256 + tid) * 8;
        float4 a = *(const float4*)&mem[i];
        float4 b = *(const float4*)&mem[i + 4];
        uint32_t pk[4];
        CVT_BF16X2(pk[0], a.y, a.x);
        CVT_BF16X2(pk[1], a.w, a.z);
        CVT_BF16X2(pk[2], b.y, b.x);
        CVT_BF16X2(pk[3], b.w, b.z);
        *(uint4*)&g_mem_bf[i] = *(uint4*)pk;
        if (bid < 8) g_rowmax[bid * 256 + tid] = 0u;
        return;
    }

    // ---- proj part (R4-certified) ------------------------------------------
    const int pb = bid - 2048;
    const int tx = tid & 15, ty = tid >> 4;
    const int n0 = (pb & 3) * 64;          // PROJ/64 = 4
    const int b0 = (pb >> 2) * 64;

    unsigned long long acc01[4], acc23[4];
    #pragma unroll
    for (int i = 0; i < 4; i++) { acc01[i] = 0ull; acc23[i] = 0ull; }

    for (int kt = 0; kt < FLAT_IN; kt += 32) {
        #pragma unroll
        for (int p = 0; p < 2; p++) {
            int idx = p * 256 + tid;
            int r = idx >> 3, c4 = idx & 7;
            *(float4*)&As[r * 36 + c4 * 4] =
                *(const float4*)&state[(size_t)(b0 + r) * FLAT_IN + kt + c4 * 4];
        }
        #pragma unroll
        for (int p = 0; p < 2; p++) {
            int idx = p * 256 + tid;
            int r = idx >> 4, c4 = idx & 15;
            *(float4*)&Bs[r * 68 + c4 * 4] =
                *(const float4*)&rp[(size_t)(kt + r) * PROJ + n0 + c4 * 4];
        }
        __syncthreads();
        #pragma unroll
        for (int k = 0; k < 32; k++) {
            ulonglong2 bp = *(const ulonglong2*)&Bs[k * 68 + tx * 4];
            #pragma unroll
            for (int i = 0; i < 4; i++) {
                unsigned long long aa = pack2(As[(ty * 4 + i) * 36 + k]);
                ffma2(acc01[i], aa, bp.x);
                ffma2(acc23[i], aa, bp.y);
            }
        }
        __syncthreads();
    }
    #pragma unroll
    for (int i = 0; i < 4; i++) {
        float c0, c1, c2, c3;
        asm("mov.b64 {%0, %1}, %2;" : "=f"(c0), "=f"(c1) : "l"(acc01[i]));
        asm("mov.b64 {%0, %1}, %2;" : "=f"(c2), "=f"(c3) : "l"(acc23[i]));
        size_t o = (size_t)(b0 + ty * 4 + i) * PROJ + n0 + tx * 4;
        *(float4*)&g_s[o] = make_float4(c0, c1, c2, c3);
        uint32_t p0, p1;
        CVT_BF16X2(p0, c1, c0);
        CVT_BF16X2(p1, c3, c2);
        *(uint2*)&g_s_bf[o] = make_uint2(p0, p1);
    }
}

// ---------------------------------------------------------------------------
// K2: HMMA bf16 screen (R4-certified mainloop); epilogue emits per-32-head
//     fp32 maxima AND publishes the per-row max via atomicMax(g_rowmax).
// ---------------------------------------------------------------------------
__global__ __launch_bounds__(256) void sim_mma_kernel() {
    __shared__ __align__(16) __nv_bfloat16 As[2][128 * 40];
    __shared__ __align__(16) __nv_bfloat16 Bs[2][128 * 40];
    __shared__ float sbm[128][4];   // [row][wn*2 + sub], sub = 32-col half

    const int tid  = threadIdx.x;
    const int lane = tid & 31, wid = tid >> 5;
    const int wm = wid & 3, wn = wid >> 2;
    const int h0 = blockIdx.x * 128, b0 = blockIdx.y * 128;

    const __nv_bfloat16* Ag = g_s_bf   + (size_t)b0 * PROJ;
    const __nv_bfloat16* Bg = g_mem_bf + (size_t)h0 * PROJ;

    const int r0 = tid >> 2,        c0 = tid & 3;
    const int r1 = 64 + (tid >> 2), c1 = tid & 3;

    uint4 ra0, ra1, rb0, rb1;
    #define GLOAD(kt)                                                          \
        ra0 = *(const uint4*)(Ag + (size_t)r0 * PROJ + (kt) * 32 + c0 * 8);    \
        ra1 = *(const uint4*)(Ag + (size_t)r1 * PROJ + (kt) * 32 + c1 * 8);    \
        rb0 = *(const uint4*)(Bg + (size_t)r0 * PROJ + (kt) * 32 + c0 * 8);    \
        rb1 = *(const uint4*)(Bg + (size_t)r1 * PROJ + (kt) * 32 + c1 * 8)

    float acc[2][8][4];
    #pragma unroll
    for (int mt = 0; mt < 2; mt++)
        #pragma unroll
        for (int nt = 0; nt < 8; nt++)
            #pragma unroll
            for (int q = 0; q < 4; q++) acc[mt][nt][q] = 0.0f;

    const uint32_t a_smem = smem_u32(As);
    const uint32_t b_smem = smem_u32(Bs);
    const uint32_t a_row = wm * 32 + (lane & 15);
    const uint32_t a_col = (lane >> 4) * 8;
    const uint32_t b_row = wn * 64 + (lane & 7) + ((lane >> 4) << 3);
    const uint32_t b_col = ((lane >> 3) & 1) * 8;

    GLOAD(0);
    int buf = 0;
    for (int kt = 0; kt < PROJ / 32; kt++) {
        *(uint4*)&As[buf][r0 * 40 + c0 * 8] = ra0;
        *(uint4*)&As[buf][r1 * 40 + c1 * 8] = ra1;
        *(uint4*)&Bs[buf][r0 * 40 + c0 * 8] = rb0;
        *(uint4*)&Bs[buf][r1 * 40 + c1 * 8] = rb1;
        __syncthreads();
        if (kt + 1 < PROJ / 32) { GLOAD(kt + 1); }

        const uint32_t ab = a_smem + (uint32_t)buf * (128 * 40 * 2);
        const uint32_t bb = b_smem + (uint32_t)buf * (128 * 40 * 2);
        #pragma unroll
        for (int ks = 0; ks < 2; ks++) {
            uint32_t af[2][4], bf[4][4];
            #pragma unroll
            for (int mt = 0; mt < 2; mt++)
                LDSM4(af[mt], ab + ((a_row + mt * 16) * 40 + ks * 16 + a_col) * 2);
            #pragma unroll
            for (int np = 0; np < 4; np++)
                LDSM4(bf[np], bb + ((b_row + np * 16) * 40 + ks * 16 + b_col) * 2);
            #pragma unroll
            for (int mt = 0; mt < 2; mt++)
                #pragma unroll
                for (int nt = 0; nt < 8; nt++)
                    MMA_BF16(acc[mt][nt], af[mt],
                             bf[nt >> 1][(nt & 1) * 2], bf[nt >> 1][(nt & 1) * 2 + 1]);
        }
        __syncthreads();
        buf ^= 1;
    }

    // ---- epilogue: per-row max over each 32-col sub-block ------------------
    float mx[2][2][2];   // [mt][half][sub]
    #pragma unroll
    for (int mt = 0; mt < 2; mt++)
        #pragma unroll
        for (int hf = 0; hf < 2; hf++)
            #pragma unroll
            for (int sb = 0; sb < 2; sb++) mx[mt][hf][sb] = -1e30f;
    #pragma unroll
    for (int mt = 0; mt < 2; mt++)
        #pragma unroll
        for (int nt = 0; nt < 8; nt++) {
            int sb = nt >> 2;
            mx[mt][0][sb] = fmaxf(mx[mt][0][sb], fmaxf(acc[mt][nt][0], acc[mt][nt][1]));
            mx[mt][1][sb] = fmaxf(mx[mt][1][sb], fmaxf(acc[mt][nt][2], acc[mt][nt][3]));
        }
    #pragma unroll
    for (int off = 1; off <= 2; off <<= 1)
        #pragma unroll
        for (int mt = 0; mt < 2; mt++)
            #pragma unroll
            for (int hf = 0; hf < 2; hf++)
                #pragma unroll
                for (int sb = 0; sb < 2; sb++)
                    mx[mt][hf][sb] = fmaxf(mx[mt][hf][sb],
                        __shfl_xor_sync(0xFFFFFFFFu, mx[mt][hf][sb], off));
    if ((lane & 3) == 0) {
        #pragma unroll
        for (int mt = 0; mt < 2; mt++)
            #pragma unroll
            for (int hf = 0; hf < 2; hf++) {
                int r = wm * 32 + mt * 16 + hf * 8 + (lane >> 2);
                sbm[r][wn * 2 + 0] = mx[mt][hf][0];
                sbm[r][wn * 2 + 1] = mx[mt][hf][1];
            }
    }
    __syncthreads();
    #pragma unroll
    for (int p = 0; p < 2; p++) {
        int idx = p * 256 + tid;
        int r = idx >> 2, c = idx & 3;
        float v = sbm[r][c];
        g_blockmax[(size_t)(b0 + r) * NBLK + blockIdx.x * 4 + c] = v;
        atomicMax(&g_rowmax[b0 + r], okey(v));
    }
}

// ---------------------------------------------------------------------------
// K3: threshold blockmaxes against precomputed g_rowmax (phase 1 eliminated)
//     -> margin candidates -> exact fp32 rescore -> gather. (R4-certified.)
// ---------------------------------------------------------------------------
__global__ __launch_bounds__(256) void argmax_kernel(const float* __restrict__ mem,
                                                     const float* __restrict__ logits,
                                                     float* __restrict__ out) {
    __shared__ __align__(16) float s_row[PROJ];
    __shared__ int   cand[24];
    __shared__ int   ncand;
    __shared__ unsigned long long best;

    const int b = blockIdx.x, tid = threadIdx.x;
    const int lane = tid & 31, wid = tid >> 5;

    if (tid < 64)
        *(float4*)&s_row[tid * 4] = *(const float4*)&g_s[(size_t)b * PROJ + tid * 4];
    if (tid == 0) { ncand = 0; best = 0ull; }

    // row max published by sim_mma's epilogue
    const float thr = unkey(g_rowmax[b]) - 24.0f;   // margin 24 (R4-certified)

    const float* bmrow = g_blockmax + (size_t)b * NBLK;
    float v0 = bmrow[tid], v1 = bmrow[256 + tid];
    __syncthreads();   // covers ncand/best init
    if (v0 >= thr) { int p = atomicAdd(&ncand, 1); if (p < 24) cand[p] = tid; }
    if (v1 >= thr) { int p = atomicAdd(&ncand, 1); if (p < 24) cand[p] = 256 + tid; }
    __syncthreads();

    const int nc = min(ncand, 24);
    const float4 sa = *(const float4*)&s_row[lane * 4];
    const float4 sb = *(const float4*)&s_row[128 + lane * 4];
    for (int c = 0; c < nc; c++) {
        const int hbase = cand[c] * 32;
        #pragma unroll
        for (int t = 0; t < 4; t++) {
            int h = hbase + wid * 4 + t;
            const float4* mr = (const float4*)(mem + (size_t)h * PROJ);
            float4 x = __ldg(&mr[lane]);
            float4 y = __ldg(&mr[lane + 32]);
            float p = x.x * sa.x + x.y * sa.y + x.z * sa.z + x.w * sa.w
                    + y.x * sb.x + y.y * sb.y + y.z * sb.z + y.w * sb.w;
            #pragma unroll
            for (int o = 16; o >= 1; o >>= 1)
                p += __shfl_xor_sync(0xFFFFFFFFu, p, o);
            if (lane == 0) {
                unsigned long long pk =
                    ((unsigned long long)okey(p) << 32) |
                    (unsigned long long)(0xFFFFFFFFu - (unsigned)h);
                atomicMax(&best, pk);
            }
        }
    }
    __syncthreads();
    unsigned h = 0xFFFFFFFFu - (unsigned)(best & 0xFFFFFFFFull);
    if (tid < ACT)
        out[(size_t)b * ACT + tid] = logits[(size_t)h * ACT + tid];
}

// ---------------------------------------------------------------------------
extern "C" void kernel_launch(void* const* d_in, const int* in_sizes, int n_in,
                              void* d_out, int out_size) {
    const float* state  = (const float*)d_in[0];   // [2048,512]
    const float* rp     = (const float*)d_in[1];   // [512,256]
    const float* mems   = (const float*)d_in[2];   // [16384,256]
    const float* logits = (const float*)d_in[3];   // [16384,64]
    float* out = (float*)d_out;                    // [2048,64]

    prep_kernel<<<2048 + (PROJ / 64) * (BATCH / 64), 256>>>(state, rp, mems);
    sim_mma_kernel<<<dim3(HEADS / 128, BATCH / 128), 256>>>();
    argmax_kernel<<<BATCH, 256>>>(mems, logits, out);
}

// round 16
// speedup vs baseline: 1.1069x; 1.1069x over previous
#include <cuda_runtime.h>
#include <cuda_bf16.h>
#include <cstdint>

#define BATCH   2048
#define FLAT_IN 512
#define PROJ    256
#define HEADS   16384
#define ACT     64
#define NBLK    (HEADS / 32)          // 512 32-head blocks per row

// ---------------- scratch (__device__ globals; allocs are forbidden) -------
__device__ float          g_s[BATCH * PROJ];          // projected state fp32
__device__ __nv_bfloat16  g_s_bf[BATCH * PROJ];       // projected state bf16
__device__ __nv_bfloat16  g_mem_bf[HEADS * PROJ];     // memories bf16
__device__ float          g_blockmax[BATCH * NBLK];   // per-row per-32-head max
__device__ unsigned       g_rowmax[BATCH];            // per-row okey(max sim)

// ---------------- helpers ---------------------------------------------------
__device__ __forceinline__ uint32_t smem_u32(const void* p) {
    uint32_t a;
    asm("{ .reg .u64 t; cvta.to.shared.u64 t, %1; cvt.u32.u64 %0, t; }"
        : "=r"(a) : "l"(p));
    return a;
}
__device__ __forceinline__ unsigned okey(float f) {
    unsigned u = __float_as_uint(f);
    return (u & 0x80000000u) ? ~u : (u | 0x80000000u);
}
__device__ __forceinline__ float unkey(unsigned k) {
    unsigned u = (k & 0x80000000u) ? (k & 0x7FFFFFFFu) : ~k;
    return __uint_as_float(u);
}

#define LDSM4(d, addr)                                                         \
    asm volatile("ldmatrix.sync.aligned.m8n8.x4.shared.b16 {%0,%1,%2,%3}, [%4];" \
        : "=r"((d)[0]), "=r"((d)[1]), "=r"((d)[2]), "=r"((d)[3]) : "r"(addr))

#define MMA_BF16(c, a, br0, br1)                                               \
    asm volatile("mma.sync.aligned.m16n8k16.row.col.f32.bf16.bf16.f32 "        \
        "{%0,%1,%2,%3}, {%4,%5,%6,%7}, {%8,%9}, {%0,%1,%2,%3};"                \
        : "+f"((c)[0]), "+f"((c)[1]), "+f"((c)[2]), "+f"((c)[3])               \
        : "r"((a)[0]), "r"((a)[1]), "r"((a)[2]), "r"((a)[3]),                  \
          "r"(br0), "r"(br1))

#define CVT_BF16X2(dst, hi, lo)                                                \
    asm("cvt.rn.satfinite.bf16x2.f32 %0, %1, %2;" : "=r"(dst) : "f"(hi), "f"(lo))

// ---------------------------------------------------------------------------
// K0: memories fp32 -> bf16 (8 elems / thread); also zeroes g_rowmax.
// ---------------------------------------------------------------------------
__global__ __launch_bounds__(256) void conv_mem_kernel(const float* __restrict__ mem) {
    size_t i = ((size_t)blockIdx.x * 256 + threadIdx.x) * 8;
    float4 a = *(const float4*)&mem[i];
    float4 b = *(const float4*)&mem[i + 4];
    uint32_t pk[4];
    CVT_BF16X2(pk[0], a.y, a.x);
    CVT_BF16X2(pk[1], a.w, a.z);
    CVT_BF16X2(pk[2], b.y, b.x);
    CVT_BF16X2(pk[3], b.w, b.z);
    *(uint4*)&g_mem_bf[i] = *(uint4*)pk;
    if (blockIdx.x < 8) g_rowmax[blockIdx.x * 256 + threadIdx.x] = 0u;
}

// ---------------------------------------------------------------------------
// K1: s = state @ rp  [2048,512]x[512,256], plain-FFMA fp32 (R4-certified);
//     writes fp32 + bf16 copies.
// ---------------------------------------------------------------------------
__global__ __launch_bounds__(256) void proj_kernel(const float* __restrict__ state,
                                                   const float* __restrict__ rp) {
    __shared__ __align__(16) float As[64 * 36];
    __shared__ __align__(16) float Bs[32 * 68];
    const int tid = threadIdx.x;
    const int tx = tid & 15, ty = tid >> 4;
    const int n0 = blockIdx.x * 64;
    const int b0 = blockIdx.y * 64;
    float acc[4][4] = {};

    for (int kt = 0; kt < FLAT_IN; kt += 32) {
        #pragma unroll
        for (int p = 0; p < 2; p++) {
            int idx = p * 256 + tid;
            int r = idx >> 3, c4 = idx & 7;
            *(float4*)&As[r * 36 + c4 * 4] =
                *(const float4*)&state[(size_t)(b0 + r) * FLAT_IN + kt + c4 * 4];
        }
        #pragma unroll
        for (int p = 0; p < 2; p++) {
            int idx = p * 256 + tid;
            int r = idx >> 4, c4 = idx & 15;
            *(float4*)&Bs[r * 68 + c4 * 4] =
                *(const float4*)&rp[(size_t)(kt + r) * PROJ + n0 + c4 * 4];
        }
        __syncthreads();
        #pragma unroll
        for (int k = 0; k < 32; k++) {
            float4 b4 = *(const float4*)&Bs[k * 68 + tx * 4];
            #pragma unroll
            for (int i = 0; i < 4; i++) {
                float a = As[(ty * 4 + i) * 36 + k];
                acc[i][0] += a * b4.x;  acc[i][1] += a * b4.y;
                acc[i][2] += a * b4.z;  acc[i][3] += a * b4.w;
            }
        }
        __syncthreads();
    }
    #pragma unroll
    for (int i = 0; i < 4; i++) {
        size_t o = (size_t)(b0 + ty * 4 + i) * PROJ + n0 + tx * 4;
        *(float4*)&g_s[o] = make_float4(acc[i][0], acc[i][1], acc[i][2], acc[i][3]);
        uint32_t p0, p1;
        CVT_BF16X2(p0, acc[i][1], acc[i][0]);
        CVT_BF16X2(p1, acc[i][3], acc[i][2]);
        *(uint2*)&g_s_bf[o] = make_uint2(p0, p1);
    }
}

// ---------------------------------------------------------------------------
// K2: HMMA bf16 screen (R4-certified mainloop); epilogue emits per-32-head
//     fp32 maxima AND publishes the per-row max via atomicMax(g_rowmax).
// ---------------------------------------------------------------------------
__global__ __launch_bounds__(256) void sim_mma_kernel() {
    __shared__ __align__(16) __nv_bfloat16 As[2][128 * 40];
    __shared__ __align__(16) __nv_bfloat16 Bs[2][128 * 40];
    __shared__ float sbm[128][4];   // [row][wn*2 + sub], sub = 32-col half

    const int tid  = threadIdx.x;
    const int lane = tid & 31, wid = tid >> 5;
    const int wm = wid & 3, wn = wid >> 2;
    const int h0 = blockIdx.x * 128, b0 = blockIdx.y * 128;

    const __nv_bfloat16* Ag = g_s_bf   + (size_t)b0 * PROJ;
    const __nv_bfloat16* Bg = g_mem_bf + (size_t)h0 * PROJ;

    const int r0 = tid >> 2,        c0 = tid & 3;
    const int r1 = 64 + (tid >> 2), c1 = tid & 3;

    uint4 ra0, ra1, rb0, rb1;
    #define GLOAD(kt)                                                          \
        ra0 = *(const uint4*)(Ag + (size_t)r0 * PROJ + (kt) * 32 + c0 * 8);    \
        ra1 = *(const uint4*)(Ag + (size_t)r1 * PROJ + (kt) * 32 + c1 * 8);    \
        rb0 = *(const uint4*)(Bg + (size_t)r0 * PROJ + (kt) * 32 + c0 * 8);    \
        rb1 = *(const uint4*)(Bg + (size_t)r1 * PROJ + (kt) * 32 + c1 * 8)

    float acc[2][8][4];
    #pragma unroll
    for (int mt = 0; mt < 2; mt++)
        #pragma unroll
        for (int nt = 0; nt < 8; nt++)
            #pragma unroll
            for (int q = 0; q < 4; q++) acc[mt][nt][q] = 0.0f;

    const uint32_t a_smem = smem_u32(As);
    const uint32_t b_smem = smem_u32(Bs);
    const uint32_t a_row = wm * 32 + (lane & 15);
    const uint32_t a_col = (lane >> 4) * 8;
    const uint32_t b_row = wn * 64 + (lane & 7) + ((lane >> 4) << 3);
    const uint32_t b_col = ((lane >> 3) & 1) * 8;

    GLOAD(0);
    int buf = 0;
    for (int kt = 0; kt < PROJ / 32; kt++) {
        *(uint4*)&As[buf][r0 * 40 + c0 * 8] = ra0;
        *(uint4*)&As[buf][r1 * 40 + c1 * 8] = ra1;
        *(uint4*)&Bs[buf][r0 * 40 + c0 * 8] = rb0;
        *(uint4*)&Bs[buf][r1 * 40 + c1 * 8] = rb1;
        __syncthreads();
        if (kt + 1 < PROJ / 32) { GLOAD(kt + 1); }

        const uint32_t ab = a_smem + (uint32_t)buf * (128 * 40 * 2);
        const uint32_t bb = b_smem + (uint32_t)buf * (128 * 40 * 2);
        #pragma unroll
        for (int ks = 0; ks < 2; ks++) {
            uint32_t af[2][4], bf[4][4];
            #pragma unroll
            for (int mt = 0; mt < 2; mt++)
                LDSM4(af[mt], ab + ((a_row + mt * 16) * 40 + ks * 16 + a_col) * 2);
            #pragma unroll
            for (int np = 0; np < 4; np++)
                LDSM4(bf[np], bb + ((b_row + np * 16) * 40 + ks * 16 + b_col) * 2);
            #pragma unroll
            for (int mt = 0; mt < 2; mt++)
                #pragma unroll
                for (int nt = 0; nt < 8; nt++)
                    MMA_BF16(acc[mt][nt], af[mt],
                             bf[nt >> 1][(nt & 1) * 2], bf[nt >> 1][(nt & 1) * 2 + 1]);
        }
        __syncthreads();
        buf ^= 1;
    }

    // ---- epilogue: per-row max over each 32-col sub-block ------------------
    float mx[2][2][2];   // [mt][half][sub]
    #pragma unroll
    for (int mt = 0; mt < 2; mt++)
        #pragma unroll
        for (int hf = 0; hf < 2; hf++)
            #pragma unroll
            for (int sb = 0; sb < 2; sb++) mx[mt][hf][sb] = -1e30f;
    #pragma unroll
    for (int mt = 0; mt < 2; mt++)
        #pragma unroll
        for (int nt = 0; nt < 8; nt++) {
            int sb = nt >> 2;
            mx[mt][0][sb] = fmaxf(mx[mt][0][sb], fmaxf(acc[mt][nt][0], acc[mt][nt][1]));
            mx[mt][1][sb] = fmaxf(mx[mt][1][sb], fmaxf(acc[mt][nt][2], acc[mt][nt][3]));
        }
    #pragma unroll
    for (int off = 1; off <= 2; off <<= 1)
        #pragma unroll
        for (int mt = 0; mt < 2; mt++)
            #pragma unroll
            for (int hf = 0; hf < 2; hf++)
                #pragma unroll
                for (int sb = 0; sb < 2; sb++)
                    mx[mt][hf][sb] = fmaxf(mx[mt][hf][sb],
                        __shfl_xor_sync(0xFFFFFFFFu, mx[mt][hf][sb], off));
    if ((lane & 3) == 0) {
        #pragma unroll
        for (int mt = 0; mt < 2; mt++)
            #pragma unroll
            for (int hf = 0; hf < 2; hf++) {
                int r = wm * 32 + mt * 16 + hf * 8 + (lane >> 2);
                sbm[r][wn * 2 + 0] = mx[mt][hf][0];
                sbm[r][wn * 2 + 1] = mx[mt][hf][1];
            }
    }
    __syncthreads();
    #pragma unroll
    for (int p = 0; p < 2; p++) {
        int idx = p * 256 + tid;
        int r = idx >> 2, c = idx & 3;
        float v = sbm[r][c];
        g_blockmax[(size_t)(b0 + r) * NBLK + blockIdx.x * 4 + c] = v;
        atomicMax(&g_rowmax[b0 + r], okey(v));
    }
}

// ---------------------------------------------------------------------------
// K3: threshold blockmaxes against precomputed g_rowmax -> margin candidates
//     -> exact fp32 rescore -> gather. (R15-certified structure.)
// ---------------------------------------------------------------------------
__global__ __launch_bounds__(256) void argmax_kernel(const float* __restrict__ mem,
                                                     const float* __restrict__ logits,
                                                     float* __restrict__ out) {
    __shared__ __align__(16) float s_row[PROJ];
    __shared__ int   cand[24];
    __shared__ int   ncand;
    __shared__ unsigned long long best;

    const int b = blockIdx.x, tid = threadIdx.x;
    const int lane = tid & 31, wid = tid >> 5;

    if (tid < 64)
        *(float4*)&s_row[tid * 4] = *(const float4*)&g_s[(size_t)b * PROJ + tid * 4];
    if (tid == 0) { ncand = 0; best = 0ull; }

    // row max published by sim_mma's epilogue
    const float thr = unkey(g_rowmax[b]) - 24.0f;   // margin 24 (R4-certified)

    const float* bmrow = g_blockmax + (size_t)b * NBLK;
    float v0 = bmrow[tid], v1 = bmrow[256 + tid];
    __syncthreads();   // covers ncand/best init
    if (v0 >= thr) { int p = atomicAdd(&ncand, 1); if (p < 24) cand[p] = tid; }
    if (v1 >= thr) { int p = atomicAdd(&ncand, 1); if (p < 24) cand[p] = 256 + tid; }
    __syncthreads();

    const int nc = min(ncand, 24);
    const float4 sa = *(const float4*)&s_row[lane * 4];
    const float4 sb = *(const float4*)&s_row[128 + lane * 4];
    for (int c = 0; c < nc; c++) {
        const int hbase = cand[c] * 32;
        #pragma unroll
        for (int t = 0; t < 4; t++) {
            int h = hbase + wid * 4 + t;
            const float4* mr = (const float4*)(mem + (size_t)h * PROJ);
            float4 x = __ldg(&mr[lane]);
            float4 y = __ldg(&mr[lane + 32]);
            float p = x.x * sa.x + x.y * sa.y + x.z * sa.z + x.w * sa.w
                    + y.x * sb.x + y.y * sb.y + y.z * sb.z + y.w * sb.w;
            #pragma unroll
            for (int o = 16; o >= 1; o >>= 1)
                p += __shfl_xor_sync(0xFFFFFFFFu, p, o);
            if (lane == 0) {
                unsigned long long pk =
                    ((unsigned long long)okey(p) << 32) |
                    (unsigned long long)(0xFFFFFFFFu - (unsigned)h);
                atomicMax(&best, pk);
            }
        }
    }
    __syncthreads();
    unsigned h = 0xFFFFFFFFu - (unsigned)(best & 0xFFFFFFFFull);
    if (tid < ACT)
        out[(size_t)b * ACT + tid] = logits[(size_t)h * ACT + tid];
}

// ---------------------------------------------------------------------------
extern "C" void kernel_launch(void* const* d_in, const int* in_sizes, int n_in,
                              void* d_out, int out_size) {
    const float* state  = (const float*)d_in[0];   // [2048,512]
    const float* rp     = (const float*)d_in[1];   // [512,256]
    const float* mems   = (const float*)d_in[2];   // [16384,256]
    const float* logits = (const float*)d_in[3];   // [16384,64]
    float* out = (float*)d_out;                    // [2048,64]

    conv_mem_kernel<<<HEADS * PROJ / (256 * 8), 256>>>(mems);
    proj_kernel<<<dim3(PROJ / 64, BATCH / 64), 256>>>(state, rp);
    sim_mma_kernel<<<dim3(HEADS / 128, BATCH / 128), 256>>>();
    argmax_kernel<<<BATCH, 256>>>(mems, logits, out);
}

// round 17
// speedup vs baseline: 1.1808x; 1.0668x over previous
#include <cuda_runtime.h>
#include <cuda_bf16.h>
#include <cstdint>

#define BATCH   2048
#define FLAT_IN 512
#define PROJ    256
#define HEADS   16384
#define ACT     64
#define NBLK    (HEADS / 32)          // 512 32-head blocks per row

// ---------------- scratch (__device__ globals; allocs are forbidden) -------
__device__ float          g_s[BATCH * PROJ];          // projected state fp32
__device__ __nv_bfloat16  g_s_bf[BATCH * PROJ];       // projected state bf16
__device__ __nv_bfloat16  g_mem_bf[HEADS * PROJ];     // memories bf16
__device__ float          g_blockmax[BATCH * NBLK];   // per-row per-32-head max
__device__ unsigned       g_rowmax[BATCH];            // per-row okey(max sim)

// ---------------- helpers ---------------------------------------------------
__device__ __forceinline__ uint32_t smem_u32(const void* p) {
    uint32_t a;
    asm("{ .reg .u64 t; cvta.to.shared.u64 t, %1; cvt.u32.u64 %0, t; }"
        : "=r"(a) : "l"(p));
    return a;
}
__device__ __forceinline__ unsigned okey(float f) {
    unsigned u = __float_as_uint(f);
    return (u & 0x80000000u) ? ~u : (u | 0x80000000u);
}
__device__ __forceinline__ float unkey(unsigned k) {
    unsigned u = (k & 0x80000000u) ? (k & 0x7FFFFFFFu) : ~k;
    return __uint_as_float(u);
}

#define LDSM4(d, addr)                                                         \
    asm volatile("ldmatrix.sync.aligned.m8n8.x4.shared.b16 {%0,%1,%2,%3}, [%4];" \
        : "=r"((d)[0]), "=r"((d)[1]), "=r"((d)[2]), "=r"((d)[3]) : "r"(addr))

#define MMA_BF16(c, a, br0, br1)                                               \
    asm volatile("mma.sync.aligned.m16n8k16.row.col.f32.bf16.bf16.f32 "        \
        "{%0,%1,%2,%3}, {%4,%5,%6,%7}, {%8,%9}, {%0,%1,%2,%3};"                \
        : "+f"((c)[0]), "+f"((c)[1]), "+f"((c)[2]), "+f"((c)[3])               \
        : "r"((a)[0]), "r"((a)[1]), "r"((a)[2]), "r"((a)[3]),                  \
          "r"(br0), "r"(br1))

#define CVT_BF16X2(dst, hi, lo)                                                \
    asm("cvt.rn.satfinite.bf16x2.f32 %0, %1, %2;" : "=r"(dst) : "f"(hi), "f"(lo))

// ---------------------------------------------------------------------------
// K0: memories fp32 -> bf16 (8 elems / thread); also zeroes g_rowmax.
// ---------------------------------------------------------------------------
__global__ __launch_bounds__(256) void conv_mem_kernel(const float* __restrict__ mem) {
    size_t i = ((size_t)blockIdx.x * 256 + threadIdx.x) * 8;
    float4 a = *(const float4*)&mem[i];
    float4 b = *(const float4*)&mem[i + 4];
    uint32_t pk[4];
    CVT_BF16X2(pk[0], a.y, a.x);
    CVT_BF16X2(pk[1], a.w, a.z);
    CVT_BF16X2(pk[2], b.y, b.x);
    CVT_BF16X2(pk[3], b.w, b.z);
    *(uint4*)&g_mem_bf[i] = *(uint4*)pk;
    if (blockIdx.x < 8) g_rowmax[blockIdx.x * 256 + threadIdx.x] = 0u;
}

// ---------------------------------------------------------------------------
// K1: s = state @ rp  [2048,512]x[512,256], plain-FFMA fp32 (R4-certified);
//     writes fp32 + bf16 copies.
// ---------------------------------------------------------------------------
__global__ __launch_bounds__(256) void proj_kernel(const float* __restrict__ state,
                                                   const float* __restrict__ rp) {
    __shared__ __align__(16) float As[64 * 36];
    __shared__ __align__(16) float Bs[32 * 68];
    const int tid = threadIdx.x;
    const int tx = tid & 15, ty = tid >> 4;
    const int n0 = blockIdx.x * 64;
    const int b0 = blockIdx.y * 64;
    float acc[4][4] = {};

    for (int kt = 0; kt < FLAT_IN; kt += 32) {
        #pragma unroll
        for (int p = 0; p < 2; p++) {
            int idx = p * 256 + tid;
            int r = idx >> 3, c4 = idx & 7;
            *(float4*)&As[r * 36 + c4 * 4] =
                *(const float4*)&state[(size_t)(b0 + r) * FLAT_IN + kt + c4 * 4];
        }
        #pragma unroll
        for (int p = 0; p < 2; p++) {
            int idx = p * 256 + tid;
            int r = idx >> 4, c4 = idx & 15;
            *(float4*)&Bs[r * 68 + c4 * 4] =
                *(const float4*)&rp[(size_t)(kt + r) * PROJ + n0 + c4 * 4];
        }
        __syncthreads();
        #pragma unroll
        for (int k = 0; k < 32; k++) {
            float4 b4 = *(const float4*)&Bs[k * 68 + tx * 4];
            #pragma unroll
            for (int i = 0; i < 4; i++) {
                float a = As[(ty * 4 + i) * 36 + k];
                acc[i][0] += a * b4.x;  acc[i][1] += a * b4.y;
                acc[i][2] += a * b4.z;  acc[i][3] += a * b4.w;
            }
        }
        __syncthreads();
    }
    #pragma unroll
    for (int i = 0; i < 4; i++) {
        size_t o = (size_t)(b0 + ty * 4 + i) * PROJ + n0 + tx * 4;
        *(float4*)&g_s[o] = make_float4(acc[i][0], acc[i][1], acc[i][2], acc[i][3]);
        uint32_t p0, p1;
        CVT_BF16X2(p0, acc[i][1], acc[i][0]);
        CVT_BF16X2(p1, acc[i][3], acc[i][2]);
        *(uint2*)&g_s_bf[o] = make_uint2(p0, p1);
    }
}

// ---------------------------------------------------------------------------
// K2: HMMA bf16 screen (R4-certified mainloop). __launch_bounds__(256,2)
//     forces 2 CTAs/SM so barriers/epilogue hide under the co-CTA's MMAs.
//     Epilogue: per-32-head maxima + ONE rowmax atomic per row per CTA.
// ---------------------------------------------------------------------------
__global__ __launch_bounds__(256, 2) void sim_mma_kernel() {
    __shared__ __align__(16) __nv_bfloat16 As[2][128 * 40];
    __shared__ __align__(16) __nv_bfloat16 Bs[2][128 * 40];
    __shared__ float sbm[128][4];   // [row][wn*2 + sub], sub = 32-col half

    const int tid  = threadIdx.x;
    const int lane = tid & 31, wid = tid >> 5;
    const int wm = wid & 3, wn = wid >> 2;
    const int h0 = blockIdx.x * 128, b0 = blockIdx.y * 128;

    const __nv_bfloat16* Ag = g_s_bf   + (size_t)b0 * PROJ;
    const __nv_bfloat16* Bg = g_mem_bf + (size_t)h0 * PROJ;

    const int r0 = tid >> 2,        c0 = tid & 3;
    const int r1 = 64 + (tid >> 2), c1 = tid & 3;

    uint4 ra0, ra1, rb0, rb1;
    #define GLOAD(kt)                                                          \
        ra0 = *(const uint4*)(Ag + (size_t)r0 * PROJ + (kt) * 32 + c0 * 8);    \
        ra1 = *(const uint4*)(Ag + (size_t)r1 * PROJ + (kt) * 32 + c1 * 8);    \
        rb0 = *(const uint4*)(Bg + (size_t)r0 * PROJ + (kt) * 32 + c0 * 8);    \
        rb1 = *(const uint4*)(Bg + (size_t)r1 * PROJ + (kt) * 32 + c1 * 8)

    float acc[2][8][4];
    #pragma unroll
    for (int mt = 0; mt < 2; mt++)
        #pragma unroll
        for (int nt = 0; nt < 8; nt++)
            #pragma unroll
            for (int q = 0; q < 4; q++) acc[mt][nt][q] = 0.0f;

    const uint32_t a_smem = smem_u32(As);
    const uint32_t b_smem = smem_u32(Bs);
    const uint32_t a_row = wm * 32 + (lane & 15);
    const uint32_t a_col = (lane >> 4) * 8;
    const uint32_t b_row = wn * 64 + (lane & 7) + ((lane >> 4) << 3);
    const uint32_t b_col = ((lane >> 3) & 1) * 8;

    GLOAD(0);
    int buf = 0;
    for (int kt = 0; kt < PROJ / 32; kt++) {
        *(uint4*)&As[buf][r0 * 40 + c0 * 8] = ra0;
        *(uint4*)&As[buf][r1 * 40 + c1 * 8] = ra1;
        *(uint4*)&Bs[buf][r0 * 40 + c0 * 8] = rb0;
        *(uint4*)&Bs[buf][r1 * 40 + c1 * 8] = rb1;
        __syncthreads();
        if (kt + 1 < PROJ / 32) { GLOAD(kt + 1); }

        const uint32_t ab = a_smem + (uint32_t)buf * (128 * 40 * 2);
        const uint32_t bb = b_smem + (uint32_t)buf * (128 * 40 * 2);
        #pragma unroll
        for (int ks = 0; ks < 2; ks++) {
            uint32_t af[2][4], bf[4][4];
            #pragma unroll
            for (int mt = 0; mt < 2; mt++)
                LDSM4(af[mt], ab + ((a_row + mt * 16) * 40 + ks * 16 + a_col) * 2);
            #pragma unroll
            for (int np = 0; np < 4; np++)
                LDSM4(bf[np], bb + ((b_row + np * 16) * 40 + ks * 16 + b_col) * 2);
            #pragma unroll
            for (int mt = 0; mt < 2; mt++)
                #pragma unroll
                for (int nt = 0; nt < 8; nt++)
                    MMA_BF16(acc[mt][nt], af[mt],
                             bf[nt >> 1][(nt & 1) * 2], bf[nt >> 1][(nt & 1) * 2 + 1]);
        }
        __syncthreads();
        buf ^= 1;
    }

    // ---- epilogue: per-row max over each 32-col sub-block ------------------
    float mx[2][2][2];   // [mt][half][sub]
    #pragma unroll
    for (int mt = 0; mt < 2; mt++)
        #pragma unroll
        for (int hf = 0; hf < 2; hf++)
            #pragma unroll
            for (int sb = 0; sb < 2; sb++) mx[mt][hf][sb] = -1e30f;
    #pragma unroll
    for (int mt = 0; mt < 2; mt++)
        #pragma unroll
        for (int nt = 0; nt < 8; nt++) {
            int sb = nt >> 2;
            mx[mt][0][sb] = fmaxf(mx[mt][0][sb], fmaxf(acc[mt][nt][0], acc[mt][nt][1]));
            mx[mt][1][sb] = fmaxf(mx[mt][1][sb], fmaxf(acc[mt][nt][2], acc[mt][nt][3]));
        }
    #pragma unroll
    for (int off = 1; off <= 2; off <<= 1)
        #pragma unroll
        for (int mt = 0; mt < 2; mt++)
            #pragma unroll
            for (int hf = 0; hf < 2; hf++)
                #pragma unroll
                for (int sb = 0; sb < 2; sb++)
                    mx[mt][hf][sb] = fmaxf(mx[mt][hf][sb],
                        __shfl_xor_sync(0xFFFFFFFFu, mx[mt][hf][sb], off));
    if ((lane & 3) == 0) {
        #pragma unroll
        for (int mt = 0; mt < 2; mt++)
            #pragma unroll
            for (int hf = 0; hf < 2; hf++) {
                int r = wm * 32 + mt * 16 + hf * 8 + (lane >> 2);
                sbm[r][wn * 2 + 0] = mx[mt][hf][0];
                sbm[r][wn * 2 + 1] = mx[mt][hf][1];
            }
    }
    __syncthreads();
    #pragma unroll
    for (int p = 0; p < 2; p++) {
        int idx = p * 256 + tid;
        int r = idx >> 2, c = idx & 3;
        g_blockmax[(size_t)(b0 + r) * NBLK + blockIdx.x * 4 + c] = sbm[r][c];
    }
    // one rowmax atomic per row per CTA (threads 0..127), spread addresses
    if (tid < 128) {
        float v = fmaxf(fmaxf(sbm[tid][0], sbm[tid][1]),
                        fmaxf(sbm[tid][2], sbm[tid][3]));
        atomicMax(&g_rowmax[b0 + tid], okey(v));
    }
}

// ---------------------------------------------------------------------------
// K3: threshold blockmaxes against precomputed g_rowmax -> margin candidates
//     -> exact fp32 rescore -> gather. (R16-certified structure.)
// ---------------------------------------------------------------------------
__global__ __launch_bounds__(256) void argmax_kernel(const float* __restrict__ mem,
                                                     const float* __restrict__ logits,
                                                     float* __restrict__ out) {
    __shared__ __align__(16) float s_row[PROJ];
    __shared__ int   cand[24];
    __shared__ int   ncand;
    __shared__ unsigned long long best;

    const int b = blockIdx.x, tid = threadIdx.x;
    const int lane = tid & 31, wid = tid >> 5;

    if (tid < 64)
        *(float4*)&s_row[tid * 4] = *(const float4*)&g_s[(size_t)b * PROJ + tid * 4];
    if (tid == 0) { ncand = 0; best = 0ull; }

    const float thr = unkey(g_rowmax[b]) - 24.0f;   // margin 24 (R4-certified)

    const float* bmrow = g_blockmax + (size_t)b * NBLK;
    float v0 = bmrow[tid], v1 = bmrow[256 + tid];
    __syncthreads();   // covers ncand/best init
    if (v0 >= thr) { int p = atomicAdd(&ncand, 1); if (p < 24) cand[p] = tid; }
    if (v1 >= thr) { int p = atomicAdd(&ncand, 1); if (p < 24) cand[p] = 256 + tid; }
    __syncthreads();

    const int nc = min(ncand, 24);
    const float4 sa = *(const float4*)&s_row[lane * 4];
    const float4 sb = *(const float4*)&s_row[128 + lane * 4];
    for (int c = 0; c < nc; c++) {
        const int hbase = cand[c] * 32;
        #pragma unroll
        for (int t = 0; t < 4; t++) {
            int h = hbase + wid * 4 + t;
            const float4* mr = (const float4*)(mem + (size_t)h * PROJ);
            float4 x = __ldg(&mr[lane]);
            float4 y = __ldg(&mr[lane + 32]);
            float p = x.x * sa.x + x.y * sa.y + x.z * sa.z + x.w * sa.w
                    + y.x * sb.x + y.y * sb.y + y.z * sb.z + y.w * sb.w;
            #pragma unroll
            for (int o = 16; o >= 1; o >>= 1)
                p += __shfl_xor_sync(0xFFFFFFFFu, p, o);
            if (lane == 0) {
                unsigned long long pk =
                    ((unsigned long long)okey(p) << 32) |
                    (unsigned long long)(0xFFFFFFFFu - (unsigned)h);
                atomicMax(&best, pk);
            }
        }
    }
    __syncthreads();
    unsigned h = 0xFFFFFFFFu - (unsigned)(best & 0xFFFFFFFFull);
    if (tid < ACT)
        out[(size_t)b * ACT + tid] = logits[(size_t)h * ACT + tid];
}

// ---------------------------------------------------------------------------
extern "C" void kernel_launch(void* const* d_in, const int* in_sizes, int n_in,
                              void* d_out, int out_size) {
    const float* state  = (const float*)d_in[0];   // [2048,512]
    const float* rp     = (const float*)d_in[1];   // [512,256]
    const float* mems   = (const float*)d_in[2];   // [16384,256]
    const float* logits = (const float*)d_in[3];   // [16384,64]
    float* out = (float*)d_out;                    // [2048,64]

    conv_mem_kernel<<<HEADS * PROJ / (256 * 8), 256>>>(mems);
    proj_kernel<<<dim3(PROJ / 64, BATCH / 64), 256>>>(state, rp);
    sim_mma_kernel<<<dim3(HEADS / 128, BATCH / 128), 256>>>();
    argmax_kernel<<<BATCH, 256>>>(mems, logits, out);
}